// round 9
// baseline (speedup 1.0000x reference)
#include <cuda_runtime.h>
#include <cuda_bf16.h>
#include <math.h>
#include <stdint.h>

// Problem dims
#define BB 8
#define SS 4096
#define DD 512
#define VV 32000
#define LL 2
#define MM (BB*SS)          // 32768 rows
#define EPSV 1e-5f

// ---------------------------------------------------------------------------
// Scratch (device globals: allocation-free)
// ---------------------------------------------------------------------------
__device__ float g_h[MM*DD];                       // residual stream (fp32)
__device__ float g_v[MM*DD];                       // gemm1 output / scan input (fp32)
__device__ __nv_bfloat16 g_uhi[MM*DD], g_ulo[MM*DD];     // LN output, split
__device__ __nv_bfloat16 g_sthi[MM*DD], g_stlo[MM*DD];   // scan states, split
__device__ __nv_bfloat16 g_wbh[LL*DD*DD], g_wbl[LL*DD*DD];
__device__ __nv_bfloat16 g_wch[LL*DD*DD], g_wcl[LL*DD*DD];
__device__ __nv_bfloat16 g_wdh[LL*DD*DD], g_wdl[LL*DD*DD];
__device__ float g_abar[DD];
__device__ float g_bscale[DD];
__device__ float g_hf[BB*DD];

// ---------------------------------------------------------------------------
// Warp MMA helpers (sm_80+ PTX, valid on bare sm_103 target)
// ---------------------------------------------------------------------------
__device__ __forceinline__ uint32_t smem_to_u32(const void* p) {
    uint32_t a;
    asm("{ .reg .u64 t; cvta.to.shared.u64 t, %1; cvt.u32.u64 %0, t; }" : "=r"(a) : "l"(p));
    return a;
}

__device__ __forceinline__ void ldsm4(uint32_t* r, uint32_t addr) {
    asm volatile("ldmatrix.sync.aligned.m8n8.x4.shared.b16 {%0,%1,%2,%3}, [%4];"
                 : "=r"(r[0]), "=r"(r[1]), "=r"(r[2]), "=r"(r[3]) : "r"(addr));
}

__device__ __forceinline__ void mma16816(float* c, const uint32_t* a, uint32_t b0, uint32_t b1) {
    asm volatile("mma.sync.aligned.m16n8k16.row.col.f32.bf16.bf16.f32 "
                 "{%0,%1,%2,%3}, {%4,%5,%6,%7}, {%8,%9}, {%0,%1,%2,%3};"
                 : "+f"(c[0]), "+f"(c[1]), "+f"(c[2]), "+f"(c[3])
                 : "r"(a[0]), "r"(a[1]), "r"(a[2]), "r"(a[3]), "r"(b0), "r"(b1));
}

// SW128-style XOR swizzle on 128-byte rows (16B chunk index ^= row&7)
__device__ __forceinline__ uint32_t swz(uint32_t off) {
    return off ^ ((off >> 3) & 0x70);
}

// ---------------------------------------------------------------------------
// hi/lo bf16 split helpers
// ---------------------------------------------------------------------------
__device__ __forceinline__ void split_store4(float4 x, __nv_bfloat16* hi, __nv_bfloat16* lo, int i4) {
    __nv_bfloat16 h0 = __float2bfloat16(x.x), h1 = __float2bfloat16(x.y);
    __nv_bfloat16 h2 = __float2bfloat16(x.z), h3 = __float2bfloat16(x.w);
    __nv_bfloat16 l0 = __float2bfloat16(x.x - __bfloat162float(h0));
    __nv_bfloat16 l1 = __float2bfloat16(x.y - __bfloat162float(h1));
    __nv_bfloat16 l2 = __float2bfloat16(x.z - __bfloat162float(h2));
    __nv_bfloat16 l3 = __float2bfloat16(x.w - __bfloat162float(h3));
    ((__nv_bfloat162*)hi)[i4*2]   = __halves2bfloat162(h0, h1);
    ((__nv_bfloat162*)hi)[i4*2+1] = __halves2bfloat162(h2, h3);
    ((__nv_bfloat162*)lo)[i4*2]   = __halves2bfloat162(l0, l1);
    ((__nv_bfloat162*)lo)[i4*2+1] = __halves2bfloat162(l2, l3);
}

// ---------------------------------------------------------------------------
// Weight split: b_mat, c_mat, d_w (all [L,D,D]) -> hi/lo bf16
// ---------------------------------------------------------------------------
__global__ void conv_w_kernel(const float* __restrict__ b, const float* __restrict__ c,
                              const float* __restrict__ dw) {
    int i = blockIdx.x * blockDim.x + threadIdx.x;   // float4 index, LL*DD*DD/4 total
    split_store4(((const float4*)b)[i],  g_wbh, g_wbl, i);
    split_store4(((const float4*)c)[i],  g_wch, g_wcl, i);
    split_store4(((const float4*)dw)[i], g_wdh, g_wdl, i);
}

// ---------------------------------------------------------------------------
// Embedding gather: h[m, :] = emb[x[m], :]
// ---------------------------------------------------------------------------
__global__ void embed_kernel(const int* __restrict__ x, const float* __restrict__ emb) {
    int i4 = blockIdx.x * blockDim.x + threadIdx.x;
    int m  = i4 >> 7;
    int dq = i4 & 127;
    int row = x[m];
    reinterpret_cast<float4*>(g_h)[i4] =
        reinterpret_cast<const float4*>(emb + (size_t)row * DD)[dq];
}

// ---------------------------------------------------------------------------
// Per-layer scalar prep
// ---------------------------------------------------------------------------
__global__ void prep_kernel(const float* __restrict__ a_log, const float* __restrict__ dt_log) {
    int d = threadIdx.x;
    float a  = -expf(a_log[d]);
    float xl = dt_log[d];
    float dt = ((xl > 20.f) ? xl : log1pf(expf(xl))) + 1e-4f;
    float half  = 0.5f * dt * a;
    float denom = 1.f - half;
    g_abar[d]   = (1.f + half) / denom;
    g_bscale[d] = dt / denom;
}

// ---------------------------------------------------------------------------
// LayerNorm -> hi/lo bf16 u.  One warp per row.
// ---------------------------------------------------------------------------
__global__ void ln_kernel(const float* __restrict__ w, const float* __restrict__ b) {
    int warp = threadIdx.x >> 5, lane = threadIdx.x & 31;
    int r = blockIdx.x * 8 + warp;
    const float4* xr = (const float4*)(g_h + (size_t)r * DD);
    float4 xv[4];
    float s = 0.f;
#pragma unroll
    for (int j = 0; j < 4; j++) {
        xv[j] = xr[lane + 32*j];
        s += xv[j].x + xv[j].y + xv[j].z + xv[j].w;
    }
#pragma unroll
    for (int o = 16; o > 0; o >>= 1) s += __shfl_xor_sync(0xffffffffu, s, o);
    float mu = s * (1.f/DD);
    float vr = 0.f;
#pragma unroll
    for (int j = 0; j < 4; j++) {
        float t0 = xv[j].x - mu, t1 = xv[j].y - mu, t2 = xv[j].z - mu, t3 = xv[j].w - mu;
        vr += t0*t0 + t1*t1 + t2*t2 + t3*t3;
    }
#pragma unroll
    for (int o = 16; o > 0; o >>= 1) vr += __shfl_xor_sync(0xffffffffu, vr, o);
    float inv = rsqrtf(vr * (1.f/DD) + EPSV);

    __nv_bfloat16* hr = g_uhi + (size_t)r * DD;
    __nv_bfloat16* lr = g_ulo + (size_t)r * DD;
    const float4* w4 = (const float4*)w;
    const float4* b4 = (const float4*)b;
#pragma unroll
    for (int j = 0; j < 4; j++) {
        int c4 = lane + 32*j;
        float4 ww = w4[c4], bb = b4[c4];
        float4 o;
        o.x = (xv[j].x - mu) * inv * ww.x + bb.x;
        o.y = (xv[j].y - mu) * inv * ww.y + bb.y;
        o.z = (xv[j].z - mu) * inv * ww.z + bb.z;
        o.w = (xv[j].w - mu) * inv * ww.w + bb.w;
        split_store4(o, hr, lr, c4);
    }
}

// ---------------------------------------------------------------------------
// Tensor-core GEMM via mma.sync (fp32-emulated with hi/lo bf16 split).
// CTA tile 128x128, K chunks of 64 bf16.  SMEM regions per buffer:
//   Ah +0, Al +16384, Bh +32768, Bl +49152 (each 128 rows x 128 bytes, swizzled)
// mode 0: v[m,e] = bscale[e] * (u @ b_mat^T)              (nchunks = 8)
// mode 1: h[m,e] += states @ C^T + u @ Dw^T + db[e]       (nchunks = 16, K concat)
// ---------------------------------------------------------------------------
#define GSMEM_BYTES (2*65536)

__device__ __forceinline__ void stage_chunk(
    char* smem, int buf, int tid,
    const char* Ah, const char* Al, const char* Bh, const char* Bl,
    int m0, int n0, int k0b)
{
    char* base = smem + buf * 65536;
#pragma unroll
    for (int it = 0; it < 4; it++) {
        int e  = tid + it * 256;        // 0..1023
        int r  = e >> 3;
        int cb = (e & 7) << 4;
        uint32_t sw = swz((uint32_t)(r * 128 + cb));
        size_t goA = (size_t)(m0 + r) * 1024 + k0b + cb;   // 1024 B per bf16 row of 512
        size_t goB = (size_t)(n0 + r) * 1024 + k0b + cb;
        *(uint4*)(base + sw)         = *(const uint4*)(Ah + goA);
        *(uint4*)(base + 16384 + sw) = *(const uint4*)(Al + goA);
        *(uint4*)(base + 32768 + sw) = *(const uint4*)(Bh + goB);
        *(uint4*)(base + 49152 + sw) = *(const uint4*)(Bl + goB);
    }
}

__device__ __forceinline__ void compute_chunk(
    uint32_t sbuf, int lane, int warp_m, int warp_n, float acc[4][4][4])
{
    // ldmatrix address components
    int j  = lane >> 3;
    int r8 = lane & 7;
    int a_row_off = r8 + ((j & 1) << 3);       // A: j0 r0-7 c0 | j1 r8-15 c0 | j2 r0-7 c1 | j3 r8-15 c1
    int a_kc      = j >> 1;
    int b_row_off = r8 + ((j >> 1) << 3);      // B: j0 t0 c0 | j1 t0 c1 | j2 t1 c0 | j3 t1 c1
    int b_kc      = j & 1;

#pragma unroll
    for (int k16 = 0; k16 < 4; k16++) {
        uint32_t Ahf[4][4], Alf[4][4], Bhf[2][4], Blf[2][4];
#pragma unroll
        for (int mt = 0; mt < 4; mt++) {
            int row = warp_m * 64 + mt * 16 + a_row_off;
            uint32_t off = swz((uint32_t)(row * 128 + (k16 * 2 + a_kc) * 16));
            ldsm4(Ahf[mt], sbuf + off);
            ldsm4(Alf[mt], sbuf + 16384 + off);
        }
#pragma unroll
        for (int tp = 0; tp < 2; tp++) {
            int row = warp_n * 32 + tp * 16 + b_row_off;
            uint32_t off = swz((uint32_t)(row * 128 + (k16 * 2 + b_kc) * 16));
            ldsm4(Bhf[tp], sbuf + 32768 + off);
            ldsm4(Blf[tp], sbuf + 49152 + off);
        }
#pragma unroll
        for (int mt = 0; mt < 4; mt++) {
#pragma unroll
            for (int nt = 0; nt < 4; nt++) {
                int tp = nt >> 1, hh = (nt & 1) * 2;
                mma16816(acc[mt][nt], Ahf[mt], Bhf[tp][hh], Bhf[tp][hh+1]);  // hi*hi
                mma16816(acc[mt][nt], Ahf[mt], Blf[tp][hh], Blf[tp][hh+1]);  // hi*lo
                mma16816(acc[mt][nt], Alf[mt], Bhf[tp][hh], Bhf[tp][hh+1]);  // lo*hi
            }
        }
    }
}

__global__ __launch_bounds__(256, 1) void gemm_tc_kernel(int layer, int mode,
                                                         const float* __restrict__ db) {
    extern __shared__ char smem[];
    uint32_t sb = smem_to_u32(smem);
    int tid = threadIdx.x, wid = tid >> 5, lane = tid & 31;
    int warp_m = wid >> 2, warp_n = wid & 3;
    int n0 = blockIdx.x * 128, m0 = blockIdx.y * 128;

    const char *Ah[2], *Al[2], *Bh[2], *Bl[2];
    size_t woff = (size_t)layer * DD * DD * sizeof(__nv_bfloat16);
    int nchunks;
    if (mode == 0) {
        Ah[0] = Ah[1] = (const char*)g_uhi;   Al[0] = Al[1] = (const char*)g_ulo;
        Bh[0] = Bh[1] = (const char*)g_wbh + woff;
        Bl[0] = Bl[1] = (const char*)g_wbl + woff;
        nchunks = 8;
    } else {
        Ah[0] = (const char*)g_sthi;  Al[0] = (const char*)g_stlo;
        Bh[0] = (const char*)g_wch + woff;  Bl[0] = (const char*)g_wcl + woff;
        Ah[1] = (const char*)g_uhi;   Al[1] = (const char*)g_ulo;
        Bh[1] = (const char*)g_wdh + woff;  Bl[1] = (const char*)g_wdl + woff;
        nchunks = 16;
    }

    float acc[4][4][4];
#pragma unroll
    for (int a = 0; a < 4; a++)
#pragma unroll
        for (int b = 0; b < 4; b++)
#pragma unroll
            for (int c = 0; c < 4; c++) acc[a][b][c] = 0.f;

    stage_chunk(smem, 0, tid, Ah[0], Al[0], Bh[0], Bl[0], m0, n0, 0);
    __syncthreads();

    for (int c = 0; c < nchunks; c++) {
        int cn = c + 1;
        if (cn < nchunks) {
            int seg = cn >> 3;
            stage_chunk(smem, cn & 1, tid, Ah[seg], Al[seg], Bh[seg], Bl[seg],
                        m0, n0, (cn & 7) * 128);
        }
        compute_chunk(sb + (c & 1) * 65536, lane, warp_m, warp_n, acc);
        __syncthreads();
    }

    // Epilogue: c0,c1 -> row g, cols tg*2{0,1}; c2,c3 -> row g+8
    int g = lane >> 2, tg = lane & 3;
#pragma unroll
    for (int mt = 0; mt < 4; mt++) {
        int r0 = m0 + warp_m * 64 + mt * 16 + g;
#pragma unroll
        for (int nt = 0; nt < 4; nt++) {
            int col = n0 + warp_n * 32 + nt * 8 + tg * 2;
            if (mode == 0) {
                float s0 = g_bscale[col], s1 = g_bscale[col + 1];
                float2 o0 = make_float2(acc[mt][nt][0] * s0, acc[mt][nt][1] * s1);
                float2 o1 = make_float2(acc[mt][nt][2] * s0, acc[mt][nt][3] * s1);
                *(float2*)(g_v + (size_t)r0 * DD + col)       = o0;
                *(float2*)(g_v + (size_t)(r0 + 8) * DD + col) = o1;
            } else {
                float d0 = db[col], d1 = db[col + 1];
                float* p0 = g_h + (size_t)r0 * DD + col;
                float* p1 = g_h + (size_t)(r0 + 8) * DD + col;
                float2 h0 = *(float2*)p0, h1 = *(float2*)p1;
                h0.x += acc[mt][nt][0] + d0; h0.y += acc[mt][nt][1] + d1;
                h1.x += acc[mt][nt][2] + d0; h1.y += acc[mt][nt][3] + d1;
                *(float2*)p0 = h0;
                *(float2*)p1 = h1;
            }
        }
    }
}

// ---------------------------------------------------------------------------
// Diagonal recurrence: reads fp32 v, writes hi/lo bf16 states.
// ---------------------------------------------------------------------------
__global__ void scan_kernel() {
    int t = blockIdx.x * blockDim.x + threadIdx.x;  // 0..4095
    int b = t >> 9;
    int d = t & (DD - 1);
    float ab = g_abar[d];
    float st = 0.f;
    const float* p = g_v + (size_t)b * SS * DD + d;
    __nv_bfloat16* ph = g_sthi + (size_t)b * SS * DD + d;
    __nv_bfloat16* pl = g_stlo + (size_t)b * SS * DD + d;
#pragma unroll 1
    for (int s0 = 0; s0 < SS; s0 += 8) {
        float vb[8];
#pragma unroll
        for (int i = 0; i < 8; i++) vb[i] = p[(size_t)(s0 + i) * DD];
#pragma unroll
        for (int i = 0; i < 8; i++) {
            st = fmaf(st, ab, vb[i]);
            __nv_bfloat16 h = __float2bfloat16(st);
            ph[(size_t)(s0 + i) * DD] = h;
            pl[(size_t)(s0 + i) * DD] = __float2bfloat16(st - __bfloat162float(h));
        }
    }
}

// ---------------------------------------------------------------------------
// Final LN on last timestep of each batch row -> g_hf
// ---------------------------------------------------------------------------
__global__ void final_ln_kernel(const float* __restrict__ fw, const float* __restrict__ fb) {
    int warp = threadIdx.x >> 5, lane = threadIdx.x & 31;
    const float* xr = g_h + ((size_t)warp * SS + (SS - 1)) * DD;
    float xv[16];
    float s = 0.f;
#pragma unroll
    for (int j = 0; j < 16; j++) { xv[j] = xr[lane + 32*j]; s += xv[j]; }
#pragma unroll
    for (int o = 16; o > 0; o >>= 1) s += __shfl_xor_sync(0xffffffffu, s, o);
    float mu = s * (1.f/DD);
    float vr = 0.f;
#pragma unroll
    for (int j = 0; j < 16; j++) { float tt = xv[j] - mu; vr += tt*tt; }
#pragma unroll
    for (int o = 16; o > 0; o >>= 1) vr += __shfl_xor_sync(0xffffffffu, vr, o);
    float inv = rsqrtf(vr * (1.f/DD) + EPSV);
#pragma unroll
    for (int j = 0; j < 16; j++) {
        int c = lane + 32*j;
        g_hf[warp*DD + c] = (xv[j] - mu) * inv * fw[c] + fb[c];
    }
}

// ---------------------------------------------------------------------------
// Output GEMV: out[b,v] = hf[b,:] . out_w[v,:] + out_b[v]
// ---------------------------------------------------------------------------
__global__ __launch_bounds__(256) void out_kernel(
    const float* __restrict__ Wout, const float* __restrict__ bout, float* __restrict__ out)
{
    __shared__ float hf[BB][DD];
    for (int i = threadIdx.x; i < BB*DD; i += 256) hf[i >> 9][i & 511] = g_hf[i];
    __syncthreads();

    int warp = threadIdx.x >> 5, lane = threadIdx.x & 31;
    int v = blockIdx.x * 8 + warp;
    const float* wr = Wout + (size_t)v * DD;
    float ow[16];
#pragma unroll
    for (int j = 0; j < 16; j++) ow[j] = wr[lane + 32*j];
    float res[BB];
#pragma unroll
    for (int b = 0; b < BB; b++) {
        float s = 0.f;
#pragma unroll
        for (int j = 0; j < 16; j++) s = fmaf(ow[j], hf[b][lane + 32*j], s);
#pragma unroll
        for (int o = 16; o > 0; o >>= 1) s += __shfl_xor_sync(0xffffffffu, s, o);
        res[b] = s;
    }
    if (lane == 0) {
        float bb = bout[v];
#pragma unroll
        for (int b = 0; b < BB; b++) out[(size_t)b * VV + v] = res[b] + bb;
    }
}

// ---------------------------------------------------------------------------
extern "C" void kernel_launch(void* const* d_in, const int* in_sizes, int n_in,
                              void* d_out, int out_size)
{
    const int*   x      = (const int*)  d_in[0];
    const float* emb    = (const float*)d_in[1];
    const float* norm_w = (const float*)d_in[2];
    const float* norm_b = (const float*)d_in[3];
    const float* b_mat  = (const float*)d_in[4];
    const float* c_mat  = (const float*)d_in[5];
    const float* d_wm   = (const float*)d_in[6];
    const float* d_bv   = (const float*)d_in[7];
    const float* a_log  = (const float*)d_in[8];
    const float* dt_log = (const float*)d_in[9];
    const float* fn_w   = (const float*)d_in[10];
    const float* fn_b   = (const float*)d_in[11];
    const float* out_w  = (const float*)d_in[12];
    const float* out_b  = (const float*)d_in[13];
    float* out = (float*)d_out;

    // Host-side, non-stream API: capture-safe, deterministic, called every time.
    cudaFuncSetAttribute(gemm_tc_kernel,
                         cudaFuncAttributeMaxDynamicSharedMemorySize, GSMEM_BYTES);

    conv_w_kernel<<<(LL*DD*DD/4) / 256, 256>>>(b_mat, c_mat, d_wm);
    embed_kernel<<<(MM * DD / 4) / 256, 256>>>(x, emb);

    dim3 ggrid(DD / 128, MM / 128);   // (4, 256)
    for (int l = 0; l < LL; l++) {
        prep_kernel<<<1, DD>>>(a_log + l*DD, dt_log + l*DD);
        ln_kernel<<<MM / 8, 256>>>(norm_w + l*DD, norm_b + l*DD);
        gemm_tc_kernel<<<ggrid, 256, GSMEM_BYTES>>>(l, 0, nullptr);
        scan_kernel<<<16, 256>>>();
        gemm_tc_kernel<<<ggrid, 256, GSMEM_BYTES>>>(l, 1, d_bv + l*DD);
    }
    final_ln_kernel<<<1, 256>>>(fn_w, fn_b);
    out_kernel<<<VV / 8, 256>>>(out_w, out_b, out);
}

// round 14
// speedup vs baseline: 2.9482x; 2.9482x over previous
#include <cuda_runtime.h>
#include <cuda_bf16.h>
#include <math.h>
#include <stdint.h>

// Problem dims
#define BB 8
#define SS 4096
#define DD 512
#define VV 32000
#define LL 2
#define MM (BB*SS)          // 32768 rows
#define EPSV 1e-5f

// Blocked scan
#define CH 64               // chunk length (timesteps)
#define NC (SS/CH)          // 64 chunks per batch row

// ---------------------------------------------------------------------------
// Scratch (device globals: allocation-free)
// ---------------------------------------------------------------------------
__device__ float g_h[MM*DD];                       // residual stream (fp32)
__device__ float g_v[MM*DD];                       // gemm1 output / local scans (fp32)
__device__ __nv_bfloat16 g_uhi[MM*DD], g_ulo[MM*DD];     // LN output, split
__device__ __nv_bfloat16 g_sthi[MM*DD], g_stlo[MM*DD];   // scan states, split
__device__ __nv_bfloat16 g_wbh[LL*DD*DD], g_wbl[LL*DD*DD];
__device__ __nv_bfloat16 g_wch[LL*DD*DD], g_wcl[LL*DD*DD];
__device__ __nv_bfloat16 g_wdh[LL*DD*DD], g_wdl[LL*DD*DD];
__device__ float g_abar[DD];
__device__ float g_ab64[DD];                       // abar^CH
__device__ float g_bscale[DD];
__device__ float g_hf[BB*DD];
__device__ float g_e[BB*NC*DD];                    // chunk-end local states (1MB)
__device__ float g_p[BB*NC*DD];                    // exclusive chunk prefixes (1MB)

// ---------------------------------------------------------------------------
// Warp MMA + async-copy helpers (sm_80+ PTX, valid on bare sm_103 target)
// ---------------------------------------------------------------------------
__device__ __forceinline__ uint32_t smem_to_u32(const void* p) {
    uint32_t a;
    asm("{ .reg .u64 t; cvta.to.shared.u64 t, %1; cvt.u32.u64 %0, t; }" : "=r"(a) : "l"(p));
    return a;
}

__device__ __forceinline__ void ldsm4(uint32_t* r, uint32_t addr) {
    asm volatile("ldmatrix.sync.aligned.m8n8.x4.shared.b16 {%0,%1,%2,%3}, [%4];"
                 : "=r"(r[0]), "=r"(r[1]), "=r"(r[2]), "=r"(r[3]) : "r"(addr));
}

__device__ __forceinline__ void mma16816(float* c, const uint32_t* a, uint32_t b0, uint32_t b1) {
    asm volatile("mma.sync.aligned.m16n8k16.row.col.f32.bf16.bf16.f32 "
                 "{%0,%1,%2,%3}, {%4,%5,%6,%7}, {%8,%9}, {%0,%1,%2,%3};"
                 : "+f"(c[0]), "+f"(c[1]), "+f"(c[2]), "+f"(c[3])
                 : "r"(a[0]), "r"(a[1]), "r"(a[2]), "r"(a[3]), "r"(b0), "r"(b1));
}

__device__ __forceinline__ void cp_async16(uint32_t dst, const void* src) {
    asm volatile("cp.async.cg.shared.global [%0], [%1], 16;" :: "r"(dst), "l"(src));
}
#define CP_COMMIT()   asm volatile("cp.async.commit_group;" ::: "memory")
#define CP_WAIT(n)    asm volatile("cp.async.wait_group %0;" :: "n"(n) : "memory")

// SW128-style XOR swizzle on 128-byte rows (16B chunk index ^= row&7)
__device__ __forceinline__ uint32_t swz(uint32_t off) {
    return off ^ ((off >> 3) & 0x70);
}

// ---------------------------------------------------------------------------
// hi/lo bf16 split helpers
// ---------------------------------------------------------------------------
__device__ __forceinline__ void split_store4(float4 x, __nv_bfloat16* hi, __nv_bfloat16* lo, int i4) {
    __nv_bfloat16 h0 = __float2bfloat16(x.x), h1 = __float2bfloat16(x.y);
    __nv_bfloat16 h2 = __float2bfloat16(x.z), h3 = __float2bfloat16(x.w);
    __nv_bfloat16 l0 = __float2bfloat16(x.x - __bfloat162float(h0));
    __nv_bfloat16 l1 = __float2bfloat16(x.y - __bfloat162float(h1));
    __nv_bfloat16 l2 = __float2bfloat16(x.z - __bfloat162float(h2));
    __nv_bfloat16 l3 = __float2bfloat16(x.w - __bfloat162float(h3));
    ((__nv_bfloat162*)hi)[i4*2]   = __halves2bfloat162(h0, h1);
    ((__nv_bfloat162*)hi)[i4*2+1] = __halves2bfloat162(h2, h3);
    ((__nv_bfloat162*)lo)[i4*2]   = __halves2bfloat162(l0, l1);
    ((__nv_bfloat162*)lo)[i4*2+1] = __halves2bfloat162(l2, l3);
}

// ---------------------------------------------------------------------------
// Weight split: b_mat, c_mat, d_w (all [L,D,D]) -> hi/lo bf16
// ---------------------------------------------------------------------------
__global__ void conv_w_kernel(const float* __restrict__ b, const float* __restrict__ c,
                              const float* __restrict__ dw) {
    int i = blockIdx.x * blockDim.x + threadIdx.x;   // float4 index
    split_store4(((const float4*)b)[i],  g_wbh, g_wbl, i);
    split_store4(((const float4*)c)[i],  g_wch, g_wcl, i);
    split_store4(((const float4*)dw)[i], g_wdh, g_wdl, i);
}

// ---------------------------------------------------------------------------
// Embedding gather
// ---------------------------------------------------------------------------
__global__ void embed_kernel(const int* __restrict__ x, const float* __restrict__ emb) {
    int i4 = blockIdx.x * blockDim.x + threadIdx.x;
    int m  = i4 >> 7;
    int dq = i4 & 127;
    int row = x[m];
    reinterpret_cast<float4*>(g_h)[i4] =
        reinterpret_cast<const float4*>(emb + (size_t)row * DD)[dq];
}

// ---------------------------------------------------------------------------
// Per-layer scalar prep
// ---------------------------------------------------------------------------
__global__ void prep_kernel(const float* __restrict__ a_log, const float* __restrict__ dt_log) {
    int d = threadIdx.x;
    float a  = -expf(a_log[d]);
    float xl = dt_log[d];
    float dt = ((xl > 20.f) ? xl : log1pf(expf(xl))) + 1e-4f;
    float half  = 0.5f * dt * a;
    float denom = 1.f - half;
    float ab = (1.f + half) / denom;
    g_abar[d]   = ab;
    g_bscale[d] = dt / denom;
    float p = ab;
    p = p*p; p = p*p; p = p*p; p = p*p; p = p*p; p = p*p;   // ab^64
    g_ab64[d] = p;
}

// ---------------------------------------------------------------------------
// LayerNorm -> hi/lo bf16 u.  One warp per row.
// ---------------------------------------------------------------------------
__global__ void ln_kernel(const float* __restrict__ w, const float* __restrict__ b) {
    int warp = threadIdx.x >> 5, lane = threadIdx.x & 31;
    int r = blockIdx.x * 8 + warp;
    const float4* xr = (const float4*)(g_h + (size_t)r * DD);
    float4 xv[4];
    float s = 0.f;
#pragma unroll
    for (int j = 0; j < 4; j++) {
        xv[j] = xr[lane + 32*j];
        s += xv[j].x + xv[j].y + xv[j].z + xv[j].w;
    }
#pragma unroll
    for (int o = 16; o > 0; o >>= 1) s += __shfl_xor_sync(0xffffffffu, s, o);
    float mu = s * (1.f/DD);
    float vr = 0.f;
#pragma unroll
    for (int j = 0; j < 4; j++) {
        float t0 = xv[j].x - mu, t1 = xv[j].y - mu, t2 = xv[j].z - mu, t3 = xv[j].w - mu;
        vr += t0*t0 + t1*t1 + t2*t2 + t3*t3;
    }
#pragma unroll
    for (int o = 16; o > 0; o >>= 1) vr += __shfl_xor_sync(0xffffffffu, vr, o);
    float inv = rsqrtf(vr * (1.f/DD) + EPSV);

    __nv_bfloat16* hr = g_uhi + (size_t)r * DD;
    __nv_bfloat16* lr = g_ulo + (size_t)r * DD;
    const float4* w4 = (const float4*)w;
    const float4* b4 = (const float4*)b;
#pragma unroll
    for (int j = 0; j < 4; j++) {
        int c4 = lane + 32*j;
        float4 ww = w4[c4], bb = b4[c4];
        float4 o;
        o.x = (xv[j].x - mu) * inv * ww.x + bb.x;
        o.y = (xv[j].y - mu) * inv * ww.y + bb.y;
        o.z = (xv[j].z - mu) * inv * ww.z + bb.z;
        o.w = (xv[j].w - mu) * inv * ww.w + bb.w;
        split_store4(o, hr, lr, c4);
    }
}

// ---------------------------------------------------------------------------
// Tensor-core GEMM via mma.sync (fp32-emulated with hi/lo bf16 split).
// CTA tile 128x128, K chunks of 64 bf16, cp.async staging, double buffer.
// mode 0: v[m,e] = bscale[e] * (u @ b_mat^T)              (nchunks = 8)
// mode 1: h[m,e] += states @ C^T + u @ Dw^T + db[e]       (nchunks = 16, K concat)
// ---------------------------------------------------------------------------
#define GSMEM_BYTES (2*65536)

__device__ __forceinline__ void stage_chunk_async(
    uint32_t sb, int buf, int tid,
    const char* Ah, const char* Al, const char* Bh, const char* Bl,
    int m0, int n0, int k0b)
{
    uint32_t base = sb + buf * 65536;
#pragma unroll
    for (int it = 0; it < 4; it++) {
        int e  = tid + it * 256;        // 0..1023
        int r  = e >> 3;
        int cb = (e & 7) << 4;
        uint32_t sw = swz((uint32_t)(r * 128 + cb));
        size_t goA = (size_t)(m0 + r) * 1024 + k0b + cb;   // 1024 B per bf16 row of 512
        size_t goB = (size_t)(n0 + r) * 1024 + k0b + cb;
        cp_async16(base + sw,         Ah + goA);
        cp_async16(base + 16384 + sw, Al + goA);
        cp_async16(base + 32768 + sw, Bh + goB);
        cp_async16(base + 49152 + sw, Bl + goB);
    }
    CP_COMMIT();
}

__device__ __forceinline__ void compute_chunk(
    uint32_t sbuf, int lane, int warp_m, int warp_n, float acc[4][4][4])
{
    int j  = lane >> 3;
    int r8 = lane & 7;
    int a_row_off = r8 + ((j & 1) << 3);
    int a_kc      = j >> 1;
    int b_row_off = r8 + ((j >> 1) << 3);
    int b_kc      = j & 1;

#pragma unroll
    for (int k16 = 0; k16 < 4; k16++) {
        uint32_t Ahf[4][4], Alf[4][4], Bhf[2][4], Blf[2][4];
#pragma unroll
        for (int mt = 0; mt < 4; mt++) {
            int row = warp_m * 64 + mt * 16 + a_row_off;
            uint32_t off = swz((uint32_t)(row * 128 + (k16 * 2 + a_kc) * 16));
            ldsm4(Ahf[mt], sbuf + off);
            ldsm4(Alf[mt], sbuf + 16384 + off);
        }
#pragma unroll
        for (int tp = 0; tp < 2; tp++) {
            int row = warp_n * 32 + tp * 16 + b_row_off;
            uint32_t off = swz((uint32_t)(row * 128 + (k16 * 2 + b_kc) * 16));
            ldsm4(Bhf[tp], sbuf + 32768 + off);
            ldsm4(Blf[tp], sbuf + 49152 + off);
        }
#pragma unroll
        for (int mt = 0; mt < 4; mt++) {
#pragma unroll
            for (int nt = 0; nt < 4; nt++) {
                int tp = nt >> 1, hh = (nt & 1) * 2;
                mma16816(acc[mt][nt], Ahf[mt], Bhf[tp][hh], Bhf[tp][hh+1]);  // hi*hi
                mma16816(acc[mt][nt], Ahf[mt], Blf[tp][hh], Blf[tp][hh+1]);  // hi*lo
                mma16816(acc[mt][nt], Alf[mt], Bhf[tp][hh], Bhf[tp][hh+1]);  // lo*hi
            }
        }
    }
}

__global__ __launch_bounds__(256, 1) void gemm_tc_kernel(int layer, int mode,
                                                         const float* __restrict__ db) {
    extern __shared__ char smem[];
    uint32_t sb = smem_to_u32(smem);
    int tid = threadIdx.x, wid = tid >> 5, lane = tid & 31;
    int warp_m = wid >> 2, warp_n = wid & 3;
    int n0 = blockIdx.x * 128, m0 = blockIdx.y * 128;

    const char *Ah[2], *Al[2], *Bh[2], *Bl[2];
    size_t woff = (size_t)layer * DD * DD * sizeof(__nv_bfloat16);
    int nchunks;
    if (mode == 0) {
        Ah[0] = Ah[1] = (const char*)g_uhi;   Al[0] = Al[1] = (const char*)g_ulo;
        Bh[0] = Bh[1] = (const char*)g_wbh + woff;
        Bl[0] = Bl[1] = (const char*)g_wbl + woff;
        nchunks = 8;
    } else {
        Ah[0] = (const char*)g_sthi;  Al[0] = (const char*)g_stlo;
        Bh[0] = (const char*)g_wch + woff;  Bl[0] = (const char*)g_wcl + woff;
        Ah[1] = (const char*)g_uhi;   Al[1] = (const char*)g_ulo;
        Bh[1] = (const char*)g_wdh + woff;  Bl[1] = (const char*)g_wdl + woff;
        nchunks = 16;
    }

    float acc[4][4][4];
#pragma unroll
    for (int a = 0; a < 4; a++)
#pragma unroll
        for (int b = 0; b < 4; b++)
#pragma unroll
            for (int c = 0; c < 4; c++) acc[a][b][c] = 0.f;

    stage_chunk_async(sb, 0, tid, Ah[0], Al[0], Bh[0], Bl[0], m0, n0, 0);

    for (int c = 0; c < nchunks; c++) {
        int cn = c + 1;
        if (cn < nchunks) {
            int seg = cn >> 3;
            stage_chunk_async(sb, cn & 1, tid, Ah[seg], Al[seg], Bh[seg], Bl[seg],
                              m0, n0, (cn & 7) * 128);
            CP_WAIT(1);              // chunk c's group complete (older)
        } else {
            CP_WAIT(0);
        }
        __syncthreads();             // visibility of buf c to all warps
        compute_chunk(sb + (c & 1) * 65536, lane, warp_m, warp_n, acc);
        __syncthreads();             // all warps done with buf c before restage
    }

    // Epilogue
    int g = lane >> 2, tg = lane & 3;
#pragma unroll
    for (int mt = 0; mt < 4; mt++) {
        int r0 = m0 + warp_m * 64 + mt * 16 + g;
#pragma unroll
        for (int nt = 0; nt < 4; nt++) {
            int col = n0 + warp_n * 32 + nt * 8 + tg * 2;
            if (mode == 0) {
                float s0 = g_bscale[col], s1 = g_bscale[col + 1];
                float2 o0 = make_float2(acc[mt][nt][0] * s0, acc[mt][nt][1] * s1);
                float2 o1 = make_float2(acc[mt][nt][2] * s0, acc[mt][nt][3] * s1);
                *(float2*)(g_v + (size_t)r0 * DD + col)       = o0;
                *(float2*)(g_v + (size_t)(r0 + 8) * DD + col) = o1;
            } else {
                float d0 = db[col], d1 = db[col + 1];
                float* p0 = g_h + (size_t)r0 * DD + col;
                float* p1 = g_h + (size_t)(r0 + 8) * DD + col;
                float2 h0 = *(float2*)p0, h1 = *(float2*)p1;
                h0.x += acc[mt][nt][0] + d0; h0.y += acc[mt][nt][1] + d1;
                h1.x += acc[mt][nt][2] + d0; h1.y += acc[mt][nt][3] + d1;
                *(float2*)p0 = h0;
                *(float2*)p1 = h1;
            }
        }
    }
}

// ---------------------------------------------------------------------------
// Blocked parallel scan, pass 1: chunk-local scans (in place) + chunk ends.
// Grid: BB*NC blocks, 256 threads; thread owns 2 consecutive d's (float2).
// ---------------------------------------------------------------------------
__global__ __launch_bounds__(256) void scan_local_kernel() {
    int blk = blockIdx.x;
    int b = blk / NC, c = blk % NC;
    int d0 = threadIdx.x * 2;
    float2 ab = *(const float2*)(g_abar + d0);
    float2 st = make_float2(0.f, 0.f);
    float* base = g_v + ((size_t)b * SS + (size_t)c * CH) * DD + d0;
#pragma unroll 1
    for (int j0 = 0; j0 < CH; j0 += 8) {
        float2 vb[8];
#pragma unroll
        for (int i = 0; i < 8; i++) vb[i] = *(const float2*)(base + (size_t)(j0 + i) * DD);
#pragma unroll
        for (int i = 0; i < 8; i++) {
            st.x = fmaf(st.x, ab.x, vb[i].x);
            st.y = fmaf(st.y, ab.y, vb[i].y);
            *(float2*)(base + (size_t)(j0 + i) * DD) = st;
        }
    }
    *(float2*)(g_e + ((size_t)b * NC + c) * DD + d0) = st;
}

// Pass 2: scan of chunk-end states across the NC chunks (per b,d).
// Writes EXCLUSIVE prefix (state entering chunk c) to g_p.
__global__ void scan_chunks_kernel() {
    int t = blockIdx.x * blockDim.x + threadIdx.x;   // 0..4095
    int b = t >> 9;
    int d = t & (DD - 1);
    float ab64 = g_ab64[d];
    float run = 0.f;
    size_t base = (size_t)b * NC * DD + d;
#pragma unroll 1
    for (int c = 0; c < NC; c++) {
        g_p[base + (size_t)c * DD] = run;
        run = fmaf(run, ab64, g_e[base + (size_t)c * DD]);
    }
}

// Pass 3: states[s0+j] = local[j] + abar^(j+1) * prefix; write hi/lo bf16.
__global__ __launch_bounds__(256) void scan_apply_kernel() {
    int blk = blockIdx.x;
    int b = blk / NC, c = blk % NC;
    int d0 = threadIdx.x * 2;
    float2 ab  = *(const float2*)(g_abar + d0);
    float2 pre = *(const float2*)(g_p + ((size_t)b * NC + c) * DD + d0);
    float2 pw  = ab;                              // abar^(j+1), j = 0
    size_t roff = ((size_t)b * SS + (size_t)c * CH) * DD + d0;
    const float* base = g_v + roff;
#pragma unroll 1
    for (int j = 0; j < CH; j++) {
        float2 loc = *(const float2*)(base + (size_t)j * DD);
        float sx = fmaf(pw.x, pre.x, loc.x);
        float sy = fmaf(pw.y, pre.y, loc.y);
        __nv_bfloat16 hx = __float2bfloat16(sx);
        __nv_bfloat16 hy = __float2bfloat16(sy);
        __nv_bfloat16 lx = __float2bfloat16(sx - __bfloat162float(hx));
        __nv_bfloat16 ly = __float2bfloat16(sy - __bfloat162float(hy));
        *(__nv_bfloat162*)(g_sthi + roff + (size_t)j * DD) = __halves2bfloat162(hx, hy);
        *(__nv_bfloat162*)(g_stlo + roff + (size_t)j * DD) = __halves2bfloat162(lx, ly);
        pw.x *= ab.x;
        pw.y *= ab.y;
    }
}

// ---------------------------------------------------------------------------
// Final LN on last timestep of each batch row -> g_hf
// ---------------------------------------------------------------------------
__global__ void final_ln_kernel(const float* __restrict__ fw, const float* __restrict__ fb) {
    int warp = threadIdx.x >> 5, lane = threadIdx.x & 31;
    const float* xr = g_h + ((size_t)warp * SS + (SS - 1)) * DD;
    float xv[16];
    float s = 0.f;
#pragma unroll
    for (int j = 0; j < 16; j++) { xv[j] = xr[lane + 32*j]; s += xv[j]; }
#pragma unroll
    for (int o = 16; o > 0; o >>= 1) s += __shfl_xor_sync(0xffffffffu, s, o);
    float mu = s * (1.f/DD);
    float vr = 0.f;
#pragma unroll
    for (int j = 0; j < 16; j++) { float tt = xv[j] - mu; vr += tt*tt; }
#pragma unroll
    for (int o = 16; o > 0; o >>= 1) vr += __shfl_xor_sync(0xffffffffu, vr, o);
    float inv = rsqrtf(vr * (1.f/DD) + EPSV);
#pragma unroll
    for (int j = 0; j < 16; j++) {
        int c = lane + 32*j;
        g_hf[warp*DD + c] = (xv[j] - mu) * inv * fw[c] + fb[c];
    }
}

// ---------------------------------------------------------------------------
// Output GEMV: out[b,v] = hf[b,:] . out_w[v,:] + out_b[v]
// ---------------------------------------------------------------------------
__global__ __launch_bounds__(256) void out_kernel(
    const float* __restrict__ Wout, const float* __restrict__ bout, float* __restrict__ out)
{
    __shared__ float hf[BB][DD];
    for (int i = threadIdx.x; i < BB*DD; i += 256) hf[i >> 9][i & 511] = g_hf[i];
    __syncthreads();

    int warp = threadIdx.x >> 5, lane = threadIdx.x & 31;
    int v = blockIdx.x * 8 + warp;
    const float* wr = Wout + (size_t)v * DD;
    float ow[16];
#pragma unroll
    for (int j = 0; j < 16; j++) ow[j] = wr[lane + 32*j];
    float res[BB];
#pragma unroll
    for (int b = 0; b < BB; b++) {
        float s = 0.f;
#pragma unroll
        for (int j = 0; j < 16; j++) s = fmaf(ow[j], hf[b][lane + 32*j], s);
#pragma unroll
        for (int o = 16; o > 0; o >>= 1) s += __shfl_xor_sync(0xffffffffu, s, o);
        res[b] = s;
    }
    if (lane == 0) {
        float bb = bout[v];
#pragma unroll
        for (int b = 0; b < BB; b++) out[(size_t)b * VV + v] = res[b] + bb;
    }
}

// ---------------------------------------------------------------------------
extern "C" void kernel_launch(void* const* d_in, const int* in_sizes, int n_in,
                              void* d_out, int out_size)
{
    const int*   x      = (const int*)  d_in[0];
    const float* emb    = (const float*)d_in[1];
    const float* norm_w = (const float*)d_in[2];
    const float* norm_b = (const float*)d_in[3];
    const float* b_mat  = (const float*)d_in[4];
    const float* c_mat  = (const float*)d_in[5];
    const float* d_wm   = (const float*)d_in[6];
    const float* d_bv   = (const float*)d_in[7];
    const float* a_log  = (const float*)d_in[8];
    const float* dt_log = (const float*)d_in[9];
    const float* fn_w   = (const float*)d_in[10];
    const float* fn_b   = (const float*)d_in[11];
    const float* out_w  = (const float*)d_in[12];
    const float* out_b  = (const float*)d_in[13];
    float* out = (float*)d_out;

    cudaFuncSetAttribute(gemm_tc_kernel,
                         cudaFuncAttributeMaxDynamicSharedMemorySize, GSMEM_BYTES);

    conv_w_kernel<<<(LL*DD*DD/4) / 256, 256>>>(b_mat, c_mat, d_wm);
    embed_kernel<<<(MM * DD / 4) / 256, 256>>>(x, emb);

    dim3 ggrid(DD / 128, MM / 128);   // (4, 256)
    for (int l = 0; l < LL; l++) {
        prep_kernel<<<1, DD>>>(a_log + l*DD, dt_log + l*DD);
        ln_kernel<<<MM / 8, 256>>>(norm_w + l*DD, norm_b + l*DD);
        gemm_tc_kernel<<<ggrid, 256, GSMEM_BYTES>>>(l, 0, nullptr);
        scan_local_kernel<<<BB*NC, 256>>>();
        scan_chunks_kernel<<<16, 256>>>();
        scan_apply_kernel<<<BB*NC, 256>>>();
        gemm_tc_kernel<<<ggrid, 256, GSMEM_BYTES>>>(l, 1, d_bv + l*DD);
    }
    final_ln_kernel<<<1, 256>>>(fn_w, fn_b);
    out_kernel<<<VV / 8, 256>>>(out_w, out_b, out);
}

// round 15
// speedup vs baseline: 4.5823x; 1.5543x over previous
#include <cuda_runtime.h>
#include <cuda_fp16.h>
#include <math.h>
#include <stdint.h>

// Problem dims
#define BB 8
#define SS 4096
#define DD 512
#define VV 32000
#define LL 2
#define MM (BB*SS)          // 32768 rows
#define EPSV 1e-5f

// Blocked scan
#define CH 64               // chunk length (timesteps)
#define NC (SS/CH)          // 64 chunks per batch row

// ---------------------------------------------------------------------------
// Scratch (device globals: allocation-free)
// ---------------------------------------------------------------------------
__device__ float g_h[MM*DD];                       // residual stream (fp32)
__device__ float g_v[MM*DD];                       // gemm1 output (fp32)
__device__ __half g_uh[MM*DD];                     // LN output, fp16
__device__ __half g_sth[MM*DD];                    // scan states, fp16
__device__ __half g_wbh[LL*DD*DD], g_wbl[LL*DD*DD];   // weights fp16 hi/lo
__device__ __half g_wch[LL*DD*DD], g_wcl[LL*DD*DD];
__device__ __half g_wdh[LL*DD*DD], g_wdl[LL*DD*DD];
__device__ float g_abar[DD];
__device__ float g_ab64[DD];                       // abar^CH
__device__ float g_bscale[DD];
__device__ float g_hf[BB*DD];
__device__ float g_e[BB*NC*DD];                    // chunk-end local states
__device__ float g_p[BB*NC*DD];                    // exclusive chunk prefixes

// ---------------------------------------------------------------------------
// Warp MMA + async-copy helpers (sm_80+ PTX, valid on bare sm_103 target)
// ---------------------------------------------------------------------------
__device__ __forceinline__ uint32_t smem_to_u32(const void* p) {
    uint32_t a;
    asm("{ .reg .u64 t; cvta.to.shared.u64 t, %1; cvt.u32.u64 %0, t; }" : "=r"(a) : "l"(p));
    return a;
}

__device__ __forceinline__ void ldsm4(uint32_t* r, uint32_t addr) {
    asm volatile("ldmatrix.sync.aligned.m8n8.x4.shared.b16 {%0,%1,%2,%3}, [%4];"
                 : "=r"(r[0]), "=r"(r[1]), "=r"(r[2]), "=r"(r[3]) : "r"(addr));
}

__device__ __forceinline__ void mma16816h(float* c, const uint32_t* a, uint32_t b0, uint32_t b1) {
    asm volatile("mma.sync.aligned.m16n8k16.row.col.f32.f16.f16.f32 "
                 "{%0,%1,%2,%3}, {%4,%5,%6,%7}, {%8,%9}, {%0,%1,%2,%3};"
                 : "+f"(c[0]), "+f"(c[1]), "+f"(c[2]), "+f"(c[3])
                 : "r"(a[0]), "r"(a[1]), "r"(a[2]), "r"(a[3]), "r"(b0), "r"(b1));
}

__device__ __forceinline__ void cp_async16(uint32_t dst, const void* src) {
    asm volatile("cp.async.cg.shared.global [%0], [%1], 16;" :: "r"(dst), "l"(src));
}
#define CP_COMMIT()   asm volatile("cp.async.commit_group;" ::: "memory")
#define CP_WAIT(n)    asm volatile("cp.async.wait_group %0;" :: "n"(n) : "memory")

// SW128-style XOR swizzle on 128-byte rows (16B chunk index ^= row&7)
__device__ __forceinline__ uint32_t swz(uint32_t off) {
    return off ^ ((off >> 3) & 0x70);
}

// ---------------------------------------------------------------------------
// Weight split: b_mat, c_mat, d_w (all [L,D,D]) -> fp16 hi/lo
// ---------------------------------------------------------------------------
__device__ __forceinline__ void split_store4h(float4 x, __half* hi, __half* lo, int i4) {
    __half h0 = __float2half(x.x), h1 = __float2half(x.y);
    __half h2 = __float2half(x.z), h3 = __float2half(x.w);
    __half l0 = __float2half(x.x - __half2float(h0));
    __half l1 = __float2half(x.y - __half2float(h1));
    __half l2 = __float2half(x.z - __half2float(h2));
    __half l3 = __float2half(x.w - __half2float(h3));
    ((__half2*)hi)[i4*2]   = __halves2half2(h0, h1);
    ((__half2*)hi)[i4*2+1] = __halves2half2(h2, h3);
    ((__half2*)lo)[i4*2]   = __halves2half2(l0, l1);
    ((__half2*)lo)[i4*2+1] = __halves2half2(l2, l3);
}

__global__ void conv_w_kernel(const float* __restrict__ b, const float* __restrict__ c,
                              const float* __restrict__ dw) {
    int i = blockIdx.x * blockDim.x + threadIdx.x;   // float4 index
    split_store4h(((const float4*)b)[i],  g_wbh, g_wbl, i);
    split_store4h(((const float4*)c)[i],  g_wch, g_wcl, i);
    split_store4h(((const float4*)dw)[i], g_wdh, g_wdl, i);
}

// ---------------------------------------------------------------------------
// Embedding gather
// ---------------------------------------------------------------------------
__global__ void embed_kernel(const int* __restrict__ x, const float* __restrict__ emb) {
    int i4 = blockIdx.x * blockDim.x + threadIdx.x;
    int m  = i4 >> 7;
    int dq = i4 & 127;
    int row = x[m];
    reinterpret_cast<float4*>(g_h)[i4] =
        reinterpret_cast<const float4*>(emb + (size_t)row * DD)[dq];
}

// ---------------------------------------------------------------------------
// Per-layer scalar prep
// ---------------------------------------------------------------------------
__global__ void prep_kernel(const float* __restrict__ a_log, const float* __restrict__ dt_log) {
    int d = threadIdx.x;
    float a  = -expf(a_log[d]);
    float xl = dt_log[d];
    float dt = ((xl > 20.f) ? xl : log1pf(expf(xl))) + 1e-4f;
    float half  = 0.5f * dt * a;
    float denom = 1.f - half;
    float ab = (1.f + half) / denom;
    g_abar[d]   = ab;
    g_bscale[d] = dt / denom;
    float p = ab;
    p = p*p; p = p*p; p = p*p; p = p*p; p = p*p; p = p*p;   // ab^64
    g_ab64[d] = p;
}

// ---------------------------------------------------------------------------
// LayerNorm -> fp16 u.  One warp per row.
// ---------------------------------------------------------------------------
__global__ void ln_kernel(const float* __restrict__ w, const float* __restrict__ b) {
    int warp = threadIdx.x >> 5, lane = threadIdx.x & 31;
    int r = blockIdx.x * 8 + warp;
    const float4* xr = (const float4*)(g_h + (size_t)r * DD);
    float4 xv[4];
    float s = 0.f;
#pragma unroll
    for (int j = 0; j < 4; j++) {
        xv[j] = xr[lane + 32*j];
        s += xv[j].x + xv[j].y + xv[j].z + xv[j].w;
    }
#pragma unroll
    for (int o = 16; o > 0; o >>= 1) s += __shfl_xor_sync(0xffffffffu, s, o);
    float mu = s * (1.f/DD);
    float vr = 0.f;
#pragma unroll
    for (int j = 0; j < 4; j++) {
        float t0 = xv[j].x - mu, t1 = xv[j].y - mu, t2 = xv[j].z - mu, t3 = xv[j].w - mu;
        vr += t0*t0 + t1*t1 + t2*t2 + t3*t3;
    }
#pragma unroll
    for (int o = 16; o > 0; o >>= 1) vr += __shfl_xor_sync(0xffffffffu, vr, o);
    float inv = rsqrtf(vr * (1.f/DD) + EPSV);

    __half2* hr = (__half2*)(g_uh + (size_t)r * DD);
    const float4* w4 = (const float4*)w;
    const float4* b4 = (const float4*)b;
#pragma unroll
    for (int j = 0; j < 4; j++) {
        int c4 = lane + 32*j;
        float4 ww = w4[c4], bb = b4[c4];
        float ox = (xv[j].x - mu) * inv * ww.x + bb.x;
        float oy = (xv[j].y - mu) * inv * ww.y + bb.y;
        float oz = (xv[j].z - mu) * inv * ww.z + bb.z;
        float ow = (xv[j].w - mu) * inv * ww.w + bb.w;
        hr[c4*2]   = __floats2half2_rn(ox, oy);
        hr[c4*2+1] = __floats2half2_rn(oz, ow);
    }
}

// ---------------------------------------------------------------------------
// Tensor-core GEMM via mma.sync, fp16 activations x fp16 hi/lo weights.
// CTA tile 128x128, K chunks of 64 fp16, cp.async staging, double buffer.
//   SMEM regions per buffer: A +0 (16KB), Bh +16384, Bl +32768 -> 48KB/buf
// mode 0: v[m,e] = bscale[e] * (u @ b_mat^T)              (nchunks = 8)
// mode 1: h[m,e] += states @ C^T + u @ Dw^T + db[e]       (nchunks = 16, K concat)
// ---------------------------------------------------------------------------
#define BUFB 49152
#define GSMEM_BYTES (2*BUFB)

__device__ __forceinline__ void stage_chunk_async(
    uint32_t sb, int buf, int tid,
    const char* A, const char* Bh, const char* Bl,
    int m0, int n0, int k0b)
{
    uint32_t base = sb + buf * BUFB;
#pragma unroll
    for (int it = 0; it < 4; it++) {
        int e  = tid + it * 256;        // 0..1023
        int r  = e >> 3;
        int cb = (e & 7) << 4;
        uint32_t sw = swz((uint32_t)(r * 128 + cb));
        size_t goA = (size_t)(m0 + r) * 1024 + k0b + cb;   // 1024 B per fp16 row of 512
        size_t goB = (size_t)(n0 + r) * 1024 + k0b + cb;
        cp_async16(base + sw,         A  + goA);
        cp_async16(base + 16384 + sw, Bh + goB);
        cp_async16(base + 32768 + sw, Bl + goB);
    }
    CP_COMMIT();
}

__device__ __forceinline__ void compute_chunk(
    uint32_t sbuf, int lane, int warp_m, int warp_n, float acc[4][4][4])
{
    int j  = lane >> 3;
    int r8 = lane & 7;
    int a_row_off = r8 + ((j & 1) << 3);
    int a_kc      = j >> 1;
    int b_row_off = r8 + ((j >> 1) << 3);
    int b_kc      = j & 1;

#pragma unroll
    for (int k16 = 0; k16 < 4; k16++) {
        uint32_t Af[4][4], Bhf[2][4], Blf[2][4];
#pragma unroll
        for (int mt = 0; mt < 4; mt++) {
            int row = warp_m * 64 + mt * 16 + a_row_off;
            uint32_t off = swz((uint32_t)(row * 128 + (k16 * 2 + a_kc) * 16));
            ldsm4(Af[mt], sbuf + off);
        }
#pragma unroll
        for (int tp = 0; tp < 2; tp++) {
            int row = warp_n * 32 + tp * 16 + b_row_off;
            uint32_t off = swz((uint32_t)(row * 128 + (k16 * 2 + b_kc) * 16));
            ldsm4(Bhf[tp], sbuf + 16384 + off);
            ldsm4(Blf[tp], sbuf + 32768 + off);
        }
#pragma unroll
        for (int mt = 0; mt < 4; mt++) {
#pragma unroll
            for (int nt = 0; nt < 4; nt++) {
                int tp = nt >> 1, hh = (nt & 1) * 2;
                mma16816h(acc[mt][nt], Af[mt], Bhf[tp][hh], Bhf[tp][hh+1]);  // x * w_hi
                mma16816h(acc[mt][nt], Af[mt], Blf[tp][hh], Blf[tp][hh+1]);  // x * w_lo
            }
        }
    }
}

__global__ __launch_bounds__(256, 2) void gemm_tc_kernel(int layer, int mode,
                                                         const float* __restrict__ db) {
    extern __shared__ char smem[];
    uint32_t sb = smem_to_u32(smem);
    int tid = threadIdx.x, wid = tid >> 5, lane = tid & 31;
    int warp_m = wid >> 2, warp_n = wid & 3;
    int n0 = blockIdx.x * 128, m0 = blockIdx.y * 128;

    const char *A[2], *Bh[2], *Bl[2];
    size_t woff = (size_t)layer * DD * DD * sizeof(__half);
    int nchunks;
    if (mode == 0) {
        A[0] = A[1] = (const char*)g_uh;
        Bh[0] = Bh[1] = (const char*)g_wbh + woff;
        Bl[0] = Bl[1] = (const char*)g_wbl + woff;
        nchunks = 8;
    } else {
        A[0] = (const char*)g_sth;
        Bh[0] = (const char*)g_wch + woff;  Bl[0] = (const char*)g_wcl + woff;
        A[1] = (const char*)g_uh;
        Bh[1] = (const char*)g_wdh + woff;  Bl[1] = (const char*)g_wdl + woff;
        nchunks = 16;
    }

    float acc[4][4][4];
#pragma unroll
    for (int a = 0; a < 4; a++)
#pragma unroll
        for (int b = 0; b < 4; b++)
#pragma unroll
            for (int c = 0; c < 4; c++) acc[a][b][c] = 0.f;

    stage_chunk_async(sb, 0, tid, A[0], Bh[0], Bl[0], m0, n0, 0);

    for (int c = 0; c < nchunks; c++) {
        int cn = c + 1;
        if (cn < nchunks) {
            int seg = cn >> 3;
            stage_chunk_async(sb, cn & 1, tid, A[seg], Bh[seg], Bl[seg],
                              m0, n0, (cn & 7) * 128);
            CP_WAIT(1);              // chunk c's group complete (older)
        } else {
            CP_WAIT(0);
        }
        __syncthreads();             // visibility of buf c to all warps
        compute_chunk(sb + (c & 1) * BUFB, lane, warp_m, warp_n, acc);
        __syncthreads();             // all warps done with buf c before restage
    }

    // Epilogue
    int g = lane >> 2, tg = lane & 3;
#pragma unroll
    for (int mt = 0; mt < 4; mt++) {
        int r0 = m0 + warp_m * 64 + mt * 16 + g;
#pragma unroll
        for (int nt = 0; nt < 4; nt++) {
            int col = n0 + warp_n * 32 + nt * 8 + tg * 2;
            if (mode == 0) {
                float s0 = g_bscale[col], s1 = g_bscale[col + 1];
                float2 o0 = make_float2(acc[mt][nt][0] * s0, acc[mt][nt][1] * s1);
                float2 o1 = make_float2(acc[mt][nt][2] * s0, acc[mt][nt][3] * s1);
                *(float2*)(g_v + (size_t)r0 * DD + col)       = o0;
                *(float2*)(g_v + (size_t)(r0 + 8) * DD + col) = o1;
            } else {
                float d0 = db[col], d1 = db[col + 1];
                float* p0 = g_h + (size_t)r0 * DD + col;
                float* p1 = g_h + (size_t)(r0 + 8) * DD + col;
                float2 h0 = *(float2*)p0, h1 = *(float2*)p1;
                h0.x += acc[mt][nt][0] + d0; h0.y += acc[mt][nt][1] + d1;
                h1.x += acc[mt][nt][2] + d0; h1.y += acc[mt][nt][3] + d1;
                *(float2*)p0 = h0;
                *(float2*)p1 = h1;
            }
        }
    }
}

// ---------------------------------------------------------------------------
// Blocked parallel scan.
// Pass 1: chunk-end states only (read g_v, write g_e; no local writeback).
// ---------------------------------------------------------------------------
__global__ __launch_bounds__(256) void scan_ends_kernel() {
    int blk = blockIdx.x;
    int b = blk / NC, c = blk % NC;
    int d0 = threadIdx.x * 2;
    float2 ab = *(const float2*)(g_abar + d0);
    float2 st = make_float2(0.f, 0.f);
    const float* base = g_v + ((size_t)b * SS + (size_t)c * CH) * DD + d0;
#pragma unroll 1
    for (int j0 = 0; j0 < CH; j0 += 8) {
        float2 vb[8];
#pragma unroll
        for (int i = 0; i < 8; i++) vb[i] = *(const float2*)(base + (size_t)(j0 + i) * DD);
#pragma unroll
        for (int i = 0; i < 8; i++) {
            st.x = fmaf(st.x, ab.x, vb[i].x);
            st.y = fmaf(st.y, ab.y, vb[i].y);
        }
    }
    *(float2*)(g_e + ((size_t)b * NC + c) * DD + d0) = st;
}

// Pass 2: scan of chunk-end states across the NC chunks (per b,d).
// Writes EXCLUSIVE prefix (state entering chunk c) to g_p.
__global__ void scan_chunks_kernel() {
    int t = blockIdx.x * blockDim.x + threadIdx.x;   // 0..4095
    int b = t >> 9;
    int d = t & (DD - 1);
    float ab64 = g_ab64[d];
    float run = 0.f;
    size_t base = (size_t)b * NC * DD + d;
#pragma unroll 1
    for (int c = 0; c < NC; c++) {
        g_p[base + (size_t)c * DD] = run;
        run = fmaf(run, ab64, g_e[base + (size_t)c * DD]);
    }
}

// Pass 3: re-run recurrence seeded with prefix; emit fp16 states.
__global__ __launch_bounds__(256) void scan_emit_kernel() {
    int blk = blockIdx.x;
    int b = blk / NC, c = blk % NC;
    int d0 = threadIdx.x * 2;
    float2 ab = *(const float2*)(g_abar + d0);
    float2 st = *(const float2*)(g_p + ((size_t)b * NC + c) * DD + d0);
    size_t roff = ((size_t)b * SS + (size_t)c * CH) * DD + d0;
    const float* base = g_v + roff;
    __half2* outp = (__half2*)(g_sth + roff);
#pragma unroll 1
    for (int j0 = 0; j0 < CH; j0 += 8) {
        float2 vb[8];
#pragma unroll
        for (int i = 0; i < 8; i++) vb[i] = *(const float2*)(base + (size_t)(j0 + i) * DD);
#pragma unroll
        for (int i = 0; i < 8; i++) {
            st.x = fmaf(st.x, ab.x, vb[i].x);
            st.y = fmaf(st.y, ab.y, vb[i].y);
            outp[(size_t)(j0 + i) * (DD/2)] = __floats2half2_rn(st.x, st.y);
        }
    }
}

// ---------------------------------------------------------------------------
// Final LN on last timestep of each batch row -> g_hf
// ---------------------------------------------------------------------------
__global__ void final_ln_kernel(const float* __restrict__ fw, const float* __restrict__ fb) {
    int warp = threadIdx.x >> 5, lane = threadIdx.x & 31;
    const float* xr = g_h + ((size_t)warp * SS + (SS - 1)) * DD;
    float xv[16];
    float s = 0.f;
#pragma unroll
    for (int j = 0; j < 16; j++) { xv[j] = xr[lane + 32*j]; s += xv[j]; }
#pragma unroll
    for (int o = 16; o > 0; o >>= 1) s += __shfl_xor_sync(0xffffffffu, s, o);
    float mu = s * (1.f/DD);
    float vr = 0.f;
#pragma unroll
    for (int j = 0; j < 16; j++) { float tt = xv[j] - mu; vr += tt*tt; }
#pragma unroll
    for (int o = 16; o > 0; o >>= 1) vr += __shfl_xor_sync(0xffffffffu, vr, o);
    float inv = rsqrtf(vr * (1.f/DD) + EPSV);
#pragma unroll
    for (int j = 0; j < 16; j++) {
        int c = lane + 32*j;
        g_hf[warp*DD + c] = (xv[j] - mu) * inv * fw[c] + fb[c];
    }
}

// ---------------------------------------------------------------------------
// Output GEMV: out[b,v] = hf[b,:] . out_w[v,:] + out_b[v]
// ---------------------------------------------------------------------------
__global__ __launch_bounds__(256) void out_kernel(
    const float* __restrict__ Wout, const float* __restrict__ bout, float* __restrict__ out)
{
    __shared__ float hf[BB][DD];
    for (int i = threadIdx.x; i < BB*DD; i += 256) hf[i >> 9][i & 511] = g_hf[i];
    __syncthreads();

    int warp = threadIdx.x >> 5, lane = threadIdx.x & 31;
    int v = blockIdx.x * 8 + warp;
    const float* wr = Wout + (size_t)v * DD;
    float ow[16];
#pragma unroll
    for (int j = 0; j < 16; j++) ow[j] = wr[lane + 32*j];
    float res[BB];
#pragma unroll
    for (int b = 0; b < BB; b++) {
        float s = 0.f;
#pragma unroll
        for (int j = 0; j < 16; j++) s = fmaf(ow[j], hf[b][lane + 32*j], s);
#pragma unroll
        for (int o = 16; o > 0; o >>= 1) s += __shfl_xor_sync(0xffffffffu, s, o);
        res[b] = s;
    }
    if (lane == 0) {
        float bb = bout[v];
#pragma unroll
        for (int b = 0; b < BB; b++) out[(size_t)b * VV + v] = res[b] + bb;
    }
}

// ---------------------------------------------------------------------------
extern "C" void kernel_launch(void* const* d_in, const int* in_sizes, int n_in,
                              void* d_out, int out_size)
{
    const int*   x      = (const int*)  d_in[0];
    const float* emb    = (const float*)d_in[1];
    const float* norm_w = (const float*)d_in[2];
    const float* norm_b = (const float*)d_in[3];
    const float* b_mat  = (const float*)d_in[4];
    const float* c_mat  = (const float*)d_in[5];
    const float* d_wm   = (const float*)d_in[6];
    const float* d_bv   = (const float*)d_in[7];
    const float* a_log  = (const float*)d_in[8];
    const float* dt_log = (const float*)d_in[9];
    const float* fn_w   = (const float*)d_in[10];
    const float* fn_b   = (const float*)d_in[11];
    const float* out_w  = (const float*)d_in[12];
    const float* out_b  = (const float*)d_in[13];
    float* out = (float*)d_out;

    cudaFuncSetAttribute(gemm_tc_kernel,
                         cudaFuncAttributeMaxDynamicSharedMemorySize, GSMEM_BYTES);

    conv_w_kernel<<<(LL*DD*DD/4) / 256, 256>>>(b_mat, c_mat, d_wm);
    embed_kernel<<<(MM * DD / 4) / 256, 256>>>(x, emb);

    dim3 ggrid(DD / 128, MM / 128);   // (4, 256)
    for (int l = 0; l < LL; l++) {
        prep_kernel<<<1, DD>>>(a_log + l*DD, dt_log + l*DD);
        ln_kernel<<<MM / 8, 256>>>(norm_w + l*DD, norm_b + l*DD);
        gemm_tc_kernel<<<ggrid, 256, GSMEM_BYTES>>>(l, 0, nullptr);
        scan_ends_kernel<<<BB*NC, 256>>>();
        scan_chunks_kernel<<<16, 256>>>();
        scan_emit_kernel<<<BB*NC, 256>>>();
        gemm_tc_kernel<<<ggrid, 256, GSMEM_BYTES>>>(l, 1, d_bv + l*DD);
    }
    final_ln_kernel<<<1, 256>>>(fn_w, fn_b);
    out_kernel<<<VV / 8, 256>>>(out_w, out_b, out);
}